// round 1
// baseline (speedup 1.0000x reference)
#include <cuda_runtime.h>

#define Bb  4
#define Ss  512
#define NHh 12
#define DHh 64
#define HID 768
#define ROWS (Bb*Ss)   // 2048

// scratch (allocation-free rule: __device__ globals)
__device__ float g_q [ROWS*HID];          // [B,S,HID]
__device__ float g_kt[ROWS*HID];          // [B,NH,DH,S]  (transposed K)
__device__ float g_v [ROWS*HID];          // [B,S,HID]

// ---------------- QKV projection GEMM ----------------
#define BM 64
#define BN 64
#define BK 16

__global__ void __launch_bounds__(256) qkv_gemm(
    const float* __restrict__ A,
    const float* __restrict__ Wq, const float* __restrict__ bq,
    const float* __restrict__ Wk, const float* __restrict__ bk,
    const float* __restrict__ Wv, const float* __restrict__ bv)
{
    const int z = blockIdx.z;
    const float* W    = (z == 0) ? Wq : (z == 1) ? Wk : Wv;
    const float* bias = (z == 0) ? bq : (z == 1) ? bk : bv;

    __shared__ float As[BK][BM + 4];   // [k][m]
    __shared__ float Ws[BK][BN];       // [k][n]

    const int tid = threadIdx.x;
    const int rowBase = blockIdx.y * BM;
    const int colBase = blockIdx.x * BN;

    const int tm = (tid / 16) * 4;
    const int tn = (tid % 16) * 4;

    // load indices
    const int lm  = tid / 4;          // 0..63
    const int lk4 = (tid % 4) * 4;    // 0,4,8,12
    const int lwk = tid / 16;         // 0..15
    const int lwn = (tid % 16) * 4;   // 0..60

    float acc[4][4] = {};

    for (int k0 = 0; k0 < HID; k0 += BK) {
        __syncthreads();
        float4 av = *(const float4*)&A[(rowBase + lm) * HID + k0 + lk4];
        As[lk4 + 0][lm] = av.x;
        As[lk4 + 1][lm] = av.y;
        As[lk4 + 2][lm] = av.z;
        As[lk4 + 3][lm] = av.w;
        *(float4*)&Ws[lwk][lwn] =
            *(const float4*)&W[(k0 + lwk) * HID + colBase + lwn];
        __syncthreads();

        #pragma unroll
        for (int k = 0; k < BK; k++) {
            float4 a = *(const float4*)&As[k][tm];
            float4 w = *(const float4*)&Ws[k][tn];
            acc[0][0] += a.x * w.x; acc[0][1] += a.x * w.y; acc[0][2] += a.x * w.z; acc[0][3] += a.x * w.w;
            acc[1][0] += a.y * w.x; acc[1][1] += a.y * w.y; acc[1][2] += a.y * w.z; acc[1][3] += a.y * w.w;
            acc[2][0] += a.z * w.x; acc[2][1] += a.z * w.y; acc[2][2] += a.z * w.z; acc[2][3] += a.z * w.w;
            acc[3][0] += a.w * w.x; acc[3][1] += a.w * w.y; acc[3][2] += a.w * w.z; acc[3][3] += a.w * w.w;
        }
    }

    #pragma unroll
    for (int i = 0; i < 4; i++) {
        const int row = rowBase + tm + i;
        #pragma unroll
        for (int j = 0; j < 4; j++) {
            const int col = colBase + tn + j;
            const float c = acc[i][j] + bias[col];
            if (z == 0) {
                g_q[row * HID + col] = c;
            } else if (z == 2) {
                g_v[row * HID + col] = c;
            } else {
                const int b = row >> 9, s = row & 511;
                const int h = col >> 6, d = col & 63;
                g_kt[((b * NHh + h) * DHh + d) * Ss + s] = c;
            }
        }
    }
}

// ---------------- fused relational attention ----------------
// CTA = one (b, q) row, all 12 heads. Online softmax over k-blocks of 128.
// dep_rel_matrix is read from HBM exactly once.
#define TK 128

__global__ void __launch_bounds__(256) attn(
    const float* __restrict__ mask,   // [B,1,1,S]
    const float* __restrict__ rel,    // [B,S,S,DH]
    float* __restrict__ out)          // [B,S,HID]
{
    const int bq   = blockIdx.x;      // b*512 + q
    const int b    = bq >> 9;
    const int tid  = threadIdx.x;
    const int wid  = tid >> 5;
    const int lane = tid & 31;

    __shared__ float q_s[HID];              // q row, pre-scaled by 1/sqrt(DH)
    __shared__ float rel_s[TK][DHh + 1];    // pad 65: conflict-free both phases
    __shared__ float sc[NHh][TK];           // scores -> probs
    __shared__ float acc_s[HID];            // running context [h*64+d]
    __shared__ float m_s[NHh], l_s[NHh], alpha_s[NHh];

    for (int i = tid; i < HID; i += 256) {
        q_s[i]   = g_q[bq * HID + i] * 0.125f;   // 1/sqrt(64)
        acc_s[i] = 0.f;
    }
    if (tid < NHh) { m_s[tid] = -1e30f; l_s[tid] = 0.f; }

    for (int kb = 0; kb < Ss; kb += TK) {
        __syncthreads();
        // stage rel block [TK, DH] (coalesced float4 load, scalar SMEM store)
        {
            const float4* rp = (const float4*)(rel + ((long)bq * Ss + kb) * DHh);
            for (int i = tid; i < TK * DHh / 4; i += 256) {
                float4 v = rp[i];
                const int k = i >> 4;
                const int d = (i & 15) << 2;
                rel_s[k][d]     = v.x;
                rel_s[k][d + 1] = v.y;
                rel_s[k][d + 2] = v.z;
                rel_s[k][d + 3] = v.w;
            }
        }
        __syncthreads();

        // --- scores: 48 units = 12 heads x 4 k-quarters, spread over 8 warps
        for (int u = wid; u < 48; u += 8) {
            const int h  = u % 12;
            const int kq = u / 12;
            const int k  = (kq << 5) + lane;
            const float* kt = g_kt + (b * NHh + h) * DHh * Ss + kb + k;
            const float* qh = q_s + h * DHh;
            float a1 = 0.f, a2 = 0.f;
            #pragma unroll 16
            for (int d = 0; d < DHh; d++) {
                const float qv = qh[d];
                a1 += qv * kt[d * Ss];
                a2 += qv * rel_s[k][d];
            }
            sc[h][k] = a1 + a2 + mask[b * Ss + kb + k];
        }
        __syncthreads();

        // --- online softmax per head
        for (int h = wid; h < NHh; h += 8) {
            float x0 = sc[h][lane], x1 = sc[h][lane + 32];
            float x2 = sc[h][lane + 64], x3 = sc[h][lane + 96];
            float mx = fmaxf(fmaxf(x0, x1), fmaxf(x2, x3));
            #pragma unroll
            for (int o = 16; o; o >>= 1) mx = fmaxf(mx, __shfl_xor_sync(0xffffffffu, mx, o));
            const float mnew = fmaxf(m_s[h], mx);
            const float p0 = __expf(x0 - mnew), p1 = __expf(x1 - mnew);
            const float p2 = __expf(x2 - mnew), p3 = __expf(x3 - mnew);
            sc[h][lane] = p0; sc[h][lane + 32] = p1;
            sc[h][lane + 64] = p2; sc[h][lane + 96] = p3;
            float ls = p0 + p1 + p2 + p3;
            #pragma unroll
            for (int o = 16; o; o >>= 1) ls += __shfl_xor_sync(0xffffffffu, ls, o);
            if (lane == 0) {
                const float alpha = __expf(m_s[h] - mnew);
                alpha_s[h] = alpha;
                l_s[h]     = l_s[h] * alpha + ls;
                m_s[h]     = mnew;
            }
        }
        __syncthreads();

        // --- accumulate ctx: acc[h][d] = acc*alpha + sum_k p[k]*(V + rel)
        for (int idx = tid; idx < NHh * DHh / 2; idx += 256) {  // 384 float2 units
            const int h  = idx >> 5;
            const int dd = (idx & 31) << 1;
            float a0 = acc_s[h * DHh + dd]     * alpha_s[h];
            float a1 = acc_s[h * DHh + dd + 1] * alpha_s[h];
            const float* vp = g_v + (long)(b * Ss + kb) * HID + h * DHh + dd;
            const float* pr = &sc[h][0];
            #pragma unroll 8
            for (int k = 0; k < TK; k++) {
                const float p = pr[k];
                const float2 vv = *(const float2*)(vp + k * HID);
                a0 += p * (vv.x + rel_s[k][dd]);
                a1 += p * (vv.y + rel_s[k][dd + 1]);
            }
            acc_s[h * DHh + dd]     = a0;
            acc_s[h * DHh + dd + 1] = a1;
        }
    }
    __syncthreads();

    for (int i = tid; i < HID; i += 256) {
        const int h = i >> 6;
        out[(long)bq * HID + i] = acc_s[i] / l_s[h];
    }
}

extern "C" void kernel_launch(void* const* d_in, const int* in_sizes, int n_in,
                              void* d_out, int out_size)
{
    const float* hidden = (const float*)d_in[0];
    const float* mask   = (const float*)d_in[1];
    const float* rel    = (const float*)d_in[2];
    const float* Wq     = (const float*)d_in[3];
    const float* bq     = (const float*)d_in[4];
    const float* Wk     = (const float*)d_in[5];
    const float* bk     = (const float*)d_in[6];
    const float* Wv     = (const float*)d_in[7];
    const float* bv     = (const float*)d_in[8];
    float* out = (float*)d_out;

    dim3 g(HID / BN, ROWS / BM, 3);
    qkv_gemm<<<g, 256>>>(hidden, Wq, bq, Wk, bk, Wv, bv);
    attn<<<ROWS, 256>>>(mask, rel, out);
}